// round 1
// baseline (speedup 1.0000x reference)
#include <cuda_runtime.h>
#include <cuda_bf16.h>
#include <cstdint>

#define N_NODES   100000
#define N_EDGES   1600000
#define D_FEAT    128
#define HIDDEN    128
#define N_CLASSES 10
#define NUM_GRAPHS 64

// ---------------- scratch (no allocs allowed) ----------------
__device__ float g_agg[(size_t)N_NODES * HIDDEN];
__device__ float g_h1 [(size_t)N_NODES * HIDDEN];
__device__ float g_h2 [(size_t)N_NODES * HIDDEN];
__device__ float g_pooled[NUM_GRAPHS * HIDDEN];

// ---------------- edge scatter: agg[dst] += h[src] ----------------
// one warp per edge; lane handles 4 floats via red.global.add.v4.f32
__global__ void __launch_bounds__(256) scatter_kernel(
    const float* __restrict__ h,
    const int*   __restrict__ ei,     // [2, E] row-major
    float*       __restrict__ agg)
{
    int gw   = (blockIdx.x * blockDim.x + threadIdx.x) >> 5;
    int lane = threadIdx.x & 31;
    if (gw >= N_EDGES) return;
    int src = __ldg(ei + gw);
    int dst = __ldg(ei + N_EDGES + gw);
    const float4* hp = reinterpret_cast<const float4*>(h + (size_t)src * HIDDEN);
    float4 v = __ldg(hp + lane);
    float* ap = agg + (size_t)dst * HIDDEN + lane * 4;
    asm volatile("red.global.add.v4.f32 [%0], {%1,%2,%3,%4};"
                 :: "l"(ap), "f"(v.x), "f"(v.y), "f"(v.z), "f"(v.w) : "memory");
}

// ---------------- fused SAGE linear: out = act(agg@Wl^T + b + h@Wr^T) ----------------
// M=N_NODES, N=128, K=256 (concat agg|h vs [Wl;Wr]); 128x128 tile, BK=16, 8x8/thread
#define BM 128
#define BN 128
#define BK 16
__global__ void __launch_bounds__(256) sage_gemm_kernel(
    const float* __restrict__ agg,
    const float* __restrict__ h,
    const float* __restrict__ Wl,   // [128 out, 128 in] row-major
    const float* __restrict__ Wr,
    const float* __restrict__ bias,
    float*       __restrict__ out,
    int do_relu)
{
    __shared__ float As[BK][BM];
    __shared__ float Bs[BK][BN];

    const int block_row = blockIdx.x * BM;
    const int tid = threadIdx.x;
    const int tx = tid & 15;   // col group
    const int ty = tid >> 4;   // row group

    float acc[8][8];
#pragma unroll
    for (int i = 0; i < 8; ++i)
#pragma unroll
        for (int j = 0; j < 8; ++j) acc[i][j] = 0.f;

    // A-tile load mapping: 128x16 floats, 256 threads, 8 floats each
    const int ar = tid >> 2;          // 0..63 (and +64)
    const int ac = (tid & 3) * 4;     // 0,4,8,12
    // W-tile load mapping: 16x128 (transposed from W rows)
    const int wj = tid >> 1;          // 0..127
    const int wc = (tid & 1) * 8;     // 0 or 8

#pragma unroll 1
    for (int kt = 0; kt < 16; ++kt) {
        const float* A = (kt < 8) ? agg : h;
        const float* W = (kt < 8) ? Wl  : Wr;
        const int k0 = (kt & 7) * BK;

        // load A tile (guard M tail)
#pragma unroll
        for (int half = 0; half < 2; ++half) {
            int r = ar + half * 64;
            int row = block_row + r;
            float4 v = make_float4(0.f, 0.f, 0.f, 0.f);
            if (row < N_NODES)
                v = *reinterpret_cast<const float4*>(A + (size_t)row * 128 + k0 + ac);
            As[ac + 0][r] = v.x;
            As[ac + 1][r] = v.y;
            As[ac + 2][r] = v.z;
            As[ac + 3][r] = v.w;
        }
        // load W tile transposed: Bs[k][j] = W[j*128 + k0 + k]
        {
            float4 v0 = *reinterpret_cast<const float4*>(W + (size_t)wj * 128 + k0 + wc);
            float4 v1 = *reinterpret_cast<const float4*>(W + (size_t)wj * 128 + k0 + wc + 4);
            Bs[wc + 0][wj] = v0.x; Bs[wc + 1][wj] = v0.y;
            Bs[wc + 2][wj] = v0.z; Bs[wc + 3][wj] = v0.w;
            Bs[wc + 4][wj] = v1.x; Bs[wc + 5][wj] = v1.y;
            Bs[wc + 6][wj] = v1.z; Bs[wc + 7][wj] = v1.w;
        }
        __syncthreads();

#pragma unroll
        for (int k = 0; k < BK; ++k) {
            float4 ra0 = *reinterpret_cast<const float4*>(&As[k][ty * 8]);
            float4 ra1 = *reinterpret_cast<const float4*>(&As[k][ty * 8 + 4]);
            float4 rb0 = *reinterpret_cast<const float4*>(&Bs[k][tx * 8]);
            float4 rb1 = *reinterpret_cast<const float4*>(&Bs[k][tx * 8 + 4]);
            float ra[8] = {ra0.x, ra0.y, ra0.z, ra0.w, ra1.x, ra1.y, ra1.z, ra1.w};
            float rb[8] = {rb0.x, rb0.y, rb0.z, rb0.w, rb1.x, rb1.y, rb1.z, rb1.w};
#pragma unroll
            for (int i = 0; i < 8; ++i)
#pragma unroll
                for (int j = 0; j < 8; ++j)
                    acc[i][j] = fmaf(ra[i], rb[j], acc[i][j]);
        }
        __syncthreads();
    }

    // epilogue
#pragma unroll
    for (int i = 0; i < 8; ++i) {
        int row = block_row + ty * 8 + i;
        if (row >= N_NODES) continue;
#pragma unroll
        for (int j = 0; j < 8; j += 4) {
            int col = tx * 8 + j;
            float4 v;
            v.x = acc[i][j + 0] + __ldg(bias + col + 0);
            v.y = acc[i][j + 1] + __ldg(bias + col + 1);
            v.z = acc[i][j + 2] + __ldg(bias + col + 2);
            v.w = acc[i][j + 3] + __ldg(bias + col + 3);
            if (do_relu) {
                v.x = fmaxf(v.x, 0.f); v.y = fmaxf(v.y, 0.f);
                v.z = fmaxf(v.z, 0.f); v.w = fmaxf(v.w, 0.f);
            }
            *reinterpret_cast<float4*>(out + (size_t)row * 128 + col) = v;
        }
    }
}

// ---------------- pooling: pooled[batch[i]] += h[i] ----------------
__global__ void __launch_bounds__(256) pool_kernel(
    const float* __restrict__ h,
    const int*   __restrict__ batch,
    float*       __restrict__ pooled)
{
    int node = (blockIdx.x * blockDim.x + threadIdx.x) >> 5;
    int lane = threadIdx.x & 31;
    if (node >= N_NODES) return;
    int g = __ldg(batch + node);
    float4 v = __ldg(reinterpret_cast<const float4*>(h + (size_t)node * HIDDEN) + lane);
    float* ap = pooled + (size_t)g * HIDDEN + lane * 4;
    asm volatile("red.global.add.v4.f32 [%0], {%1,%2,%3,%4};"
                 :: "l"(ap), "f"(v.x), "f"(v.y), "f"(v.z), "f"(v.w) : "memory");
}

// ---------------- output head: out = pooled @ Wout^T + bout ----------------
__global__ void out_kernel(
    const float* __restrict__ pooled,
    const float* __restrict__ Wout,   // [10, 128]
    const float* __restrict__ bout,
    float*       __restrict__ out)
{
    int idx = blockIdx.x * blockDim.x + threadIdx.x;
    if (idx >= NUM_GRAPHS * N_CLASSES) return;
    int g = idx / N_CLASSES;
    int c = idx % N_CLASSES;
    float s = __ldg(bout + c);
    const float* p = pooled + (size_t)g * HIDDEN;
    const float* w = Wout + (size_t)c * HIDDEN;
#pragma unroll 8
    for (int k = 0; k < HIDDEN; ++k) s = fmaf(p[k], w[k], s);
    out[idx] = s;
}

// ---------------- launch ----------------
extern "C" void kernel_launch(void* const* d_in, const int* in_sizes, int n_in,
                              void* d_out, int out_size)
{
    const float* x     = (const float*)d_in[0];
    const int*   ei    = (const int*)  d_in[1];
    const int*   batch = (const int*)  d_in[2];
    const float* W1l = (const float*)d_in[3];
    const float* b1  = (const float*)d_in[4];
    const float* W1r = (const float*)d_in[5];
    const float* W2l = (const float*)d_in[6];
    const float* b2  = (const float*)d_in[7];
    const float* W2r = (const float*)d_in[8];
    const float* W3l = (const float*)d_in[9];
    const float* b3  = (const float*)d_in[10];
    const float* W3r = (const float*)d_in[11];
    const float* Wout = (const float*)d_in[12];
    const float* bout = (const float*)d_in[13];
    float* out = (float*)d_out;

    float *agg, *h1, *h2, *pooled;
    cudaGetSymbolAddress((void**)&agg,    g_agg);
    cudaGetSymbolAddress((void**)&h1,     g_h1);
    cudaGetSymbolAddress((void**)&h2,     g_h2);
    cudaGetSymbolAddress((void**)&pooled, g_pooled);

    const size_t AGG_BYTES = (size_t)N_NODES * HIDDEN * sizeof(float);
    const int scatter_blocks = (N_EDGES * 32) / 256;            // 200000
    const int gemm_blocks    = (N_NODES + BM - 1) / BM;         // 782
    const int pool_blocks    = (N_NODES * 32 + 255) / 256;

    // layer 1: x -> h1
    cudaMemsetAsync(agg, 0, AGG_BYTES);
    scatter_kernel<<<scatter_blocks, 256>>>(x, ei, agg);
    sage_gemm_kernel<<<gemm_blocks, 256>>>(agg, x, W1l, W1r, b1, h1, 1);

    // layer 2: h1 -> h2
    cudaMemsetAsync(agg, 0, AGG_BYTES);
    scatter_kernel<<<scatter_blocks, 256>>>(h1, ei, agg);
    sage_gemm_kernel<<<gemm_blocks, 256>>>(agg, h1, W2l, W2r, b2, h2, 1);

    // layer 3: h2 -> h1 (no relu)
    cudaMemsetAsync(agg, 0, AGG_BYTES);
    scatter_kernel<<<scatter_blocks, 256>>>(h2, ei, agg);
    sage_gemm_kernel<<<gemm_blocks, 256>>>(agg, h2, W3l, W3r, b3, h1, 0);

    // pool + head
    cudaMemsetAsync(pooled, 0, NUM_GRAPHS * HIDDEN * sizeof(float));
    pool_kernel<<<pool_blocks, 256>>>(h1, batch, pooled);
    out_kernel<<<(NUM_GRAPHS * N_CLASSES + 127) / 128, 128>>>(pooled, Wout, bout, out);
}

// round 2
// speedup vs baseline: 1.2572x; 1.2572x over previous
#include <cuda_runtime.h>
#include <cuda_bf16.h>
#include <cstdint>

#define N_NODES   100000
#define N_EDGES   1600000
#define D_FEAT    128
#define HIDDEN    128
#define N_CLASSES 10
#define NUM_GRAPHS 64

// ---------------- scratch (no allocs allowed) ----------------
__device__ float g_agg[(size_t)N_NODES * HIDDEN];
__device__ float g_h1 [(size_t)N_NODES * HIDDEN];
__device__ float g_h2 [(size_t)N_NODES * HIDDEN];
__device__ float g_pooled[NUM_GRAPHS * HIDDEN];
__device__ int   g_deg [N_NODES];
__device__ int   g_off [N_NODES + 1];
__device__ int   g_cur [N_NODES];
__device__ int   g_srcs[N_EDGES];

// ---------------- CSR build ----------------
__global__ void __launch_bounds__(256) zero_deg_kernel(int* __restrict__ deg)
{
    int i = blockIdx.x * blockDim.x + threadIdx.x;
    if (i < N_NODES) deg[i] = 0;
}

__global__ void __launch_bounds__(256) hist_kernel(
    const int* __restrict__ ei, int* __restrict__ deg)
{
    int e = blockIdx.x * blockDim.x + threadIdx.x;
    if (e >= N_EDGES) return;
    atomicAdd(deg + __ldg(ei + N_EDGES + e), 1);
}

// single-block scan: 1024 threads, each owns a contiguous chunk
__global__ void __launch_bounds__(1024) scan_kernel(
    const int* __restrict__ deg, int* __restrict__ off, int* __restrict__ cur)
{
    __shared__ int part[1024];
    const int tid = threadIdx.x;
    const int CH = (N_NODES + 1023) / 1024;   // 98
    const int start = tid * CH;
    int sum = 0;
    for (int i = 0; i < CH; ++i) {
        int idx = start + i;
        if (idx < N_NODES) sum += deg[idx];
    }
    part[tid] = sum;
    __syncthreads();
    for (int d = 1; d < 1024; d <<= 1) {
        int v = (tid >= d) ? part[tid - d] : 0;
        __syncthreads();
        part[tid] += v;
        __syncthreads();
    }
    int run = tid ? part[tid - 1] : 0;
    for (int i = 0; i < CH; ++i) {
        int idx = start + i;
        if (idx <= N_NODES) {
            off[idx] = run;
            if (idx < N_NODES) cur[idx] = run;
        }
        if (idx < N_NODES) run += deg[idx];
    }
}

__global__ void __launch_bounds__(256) fill_kernel(
    const int* __restrict__ ei, int* __restrict__ cur, int* __restrict__ srcs)
{
    int e = blockIdx.x * blockDim.x + threadIdx.x;
    if (e >= N_EDGES) return;
    int src = __ldg(ei + e);
    int dst = __ldg(ei + N_EDGES + e);
    int pos = atomicAdd(cur + dst, 1);
    srcs[pos] = src;
}

// ---------------- gather aggregation: agg[n] = sum_{s in nbrs(n)} h[s] ----------------
// one warp per node, lane owns a float4 slice of the 128-float row
__global__ void __launch_bounds__(256) aggregate_kernel(
    const float* __restrict__ h,
    const int*   __restrict__ off,
    const int*   __restrict__ srcs,
    float*       __restrict__ agg)
{
    int node = (blockIdx.x * blockDim.x + threadIdx.x) >> 5;
    int lane = threadIdx.x & 31;
    if (node >= N_NODES) return;
    int b = __ldg(off + node);
    int e = __ldg(off + node + 1);
    float4 acc = make_float4(0.f, 0.f, 0.f, 0.f);
    int i = b;
    for (; i + 3 < e; i += 4) {
        int s0 = __ldg(srcs + i + 0);
        int s1 = __ldg(srcs + i + 1);
        int s2 = __ldg(srcs + i + 2);
        int s3 = __ldg(srcs + i + 3);
        float4 v0 = __ldg(reinterpret_cast<const float4*>(h + (size_t)s0 * 128) + lane);
        float4 v1 = __ldg(reinterpret_cast<const float4*>(h + (size_t)s1 * 128) + lane);
        float4 v2 = __ldg(reinterpret_cast<const float4*>(h + (size_t)s2 * 128) + lane);
        float4 v3 = __ldg(reinterpret_cast<const float4*>(h + (size_t)s3 * 128) + lane);
        acc.x += (v0.x + v1.x) + (v2.x + v3.x);
        acc.y += (v0.y + v1.y) + (v2.y + v3.y);
        acc.z += (v0.z + v1.z) + (v2.z + v3.z);
        acc.w += (v0.w + v1.w) + (v2.w + v3.w);
    }
    for (; i < e; ++i) {
        int s = __ldg(srcs + i);
        float4 v = __ldg(reinterpret_cast<const float4*>(h + (size_t)s * 128) + lane);
        acc.x += v.x; acc.y += v.y; acc.z += v.z; acc.w += v.w;
    }
    *(reinterpret_cast<float4*>(agg + (size_t)node * 128) + lane) = acc;
}

// ---------------- fused SAGE linear: out = act(agg@Wl^T + b + h@Wr^T) ----------------
#define BM 128
#define BN 128
#define BK 16
__global__ void __launch_bounds__(256) sage_gemm_kernel(
    const float* __restrict__ agg,
    const float* __restrict__ h,
    const float* __restrict__ Wl,
    const float* __restrict__ Wr,
    const float* __restrict__ bias,
    float*       __restrict__ out,
    int do_relu)
{
    __shared__ float As[BK][BM];
    __shared__ float Bs[BK][BN];

    const int block_row = blockIdx.x * BM;
    const int tid = threadIdx.x;
    const int tx = tid & 15;
    const int ty = tid >> 4;

    float acc[8][8];
#pragma unroll
    for (int i = 0; i < 8; ++i)
#pragma unroll
        for (int j = 0; j < 8; ++j) acc[i][j] = 0.f;

    const int ar = tid >> 2;
    const int ac = (tid & 3) * 4;
    const int wj = tid >> 1;
    const int wc = (tid & 1) * 8;

#pragma unroll 1
    for (int kt = 0; kt < 16; ++kt) {
        const float* A = (kt < 8) ? agg : h;
        const float* W = (kt < 8) ? Wl  : Wr;
        const int k0 = (kt & 7) * BK;

#pragma unroll
        for (int half = 0; half < 2; ++half) {
            int r = ar + half * 64;
            int row = block_row + r;
            float4 v = make_float4(0.f, 0.f, 0.f, 0.f);
            if (row < N_NODES)
                v = *reinterpret_cast<const float4*>(A + (size_t)row * 128 + k0 + ac);
            As[ac + 0][r] = v.x;
            As[ac + 1][r] = v.y;
            As[ac + 2][r] = v.z;
            As[ac + 3][r] = v.w;
        }
        {
            float4 v0 = *reinterpret_cast<const float4*>(W + (size_t)wj * 128 + k0 + wc);
            float4 v1 = *reinterpret_cast<const float4*>(W + (size_t)wj * 128 + k0 + wc + 4);
            Bs[wc + 0][wj] = v0.x; Bs[wc + 1][wj] = v0.y;
            Bs[wc + 2][wj] = v0.z; Bs[wc + 3][wj] = v0.w;
            Bs[wc + 4][wj] = v1.x; Bs[wc + 5][wj] = v1.y;
            Bs[wc + 6][wj] = v1.z; Bs[wc + 7][wj] = v1.w;
        }
        __syncthreads();

#pragma unroll
        for (int k = 0; k < BK; ++k) {
            float4 ra0 = *reinterpret_cast<const float4*>(&As[k][ty * 8]);
            float4 ra1 = *reinterpret_cast<const float4*>(&As[k][ty * 8 + 4]);
            float4 rb0 = *reinterpret_cast<const float4*>(&Bs[k][tx * 8]);
            float4 rb1 = *reinterpret_cast<const float4*>(&Bs[k][tx * 8 + 4]);
            float ra[8] = {ra0.x, ra0.y, ra0.z, ra0.w, ra1.x, ra1.y, ra1.z, ra1.w};
            float rb[8] = {rb0.x, rb0.y, rb0.z, rb0.w, rb1.x, rb1.y, rb1.z, rb1.w};
#pragma unroll
            for (int i = 0; i < 8; ++i)
#pragma unroll
                for (int j = 0; j < 8; ++j)
                    acc[i][j] = fmaf(ra[i], rb[j], acc[i][j]);
        }
        __syncthreads();
    }

#pragma unroll
    for (int i = 0; i < 8; ++i) {
        int row = block_row + ty * 8 + i;
        if (row >= N_NODES) continue;
#pragma unroll
        for (int j = 0; j < 8; j += 4) {
            int col = tx * 8 + j;
            float4 v;
            v.x = acc[i][j + 0] + __ldg(bias + col + 0);
            v.y = acc[i][j + 1] + __ldg(bias + col + 1);
            v.z = acc[i][j + 2] + __ldg(bias + col + 2);
            v.w = acc[i][j + 3] + __ldg(bias + col + 3);
            if (do_relu) {
                v.x = fmaxf(v.x, 0.f); v.y = fmaxf(v.y, 0.f);
                v.z = fmaxf(v.z, 0.f); v.w = fmaxf(v.w, 0.f);
            }
            *reinterpret_cast<float4*>(out + (size_t)row * 128 + col) = v;
        }
    }
}

// ---------------- pooling ----------------
__global__ void __launch_bounds__(256) pool_kernel(
    const float* __restrict__ h,
    const int*   __restrict__ batch,
    float*       __restrict__ pooled)
{
    int node = (blockIdx.x * blockDim.x + threadIdx.x) >> 5;
    int lane = threadIdx.x & 31;
    if (node >= N_NODES) return;
    int g = __ldg(batch + node);
    float4 v = __ldg(reinterpret_cast<const float4*>(h + (size_t)node * HIDDEN) + lane);
    float* ap = pooled + (size_t)g * HIDDEN + lane * 4;
    asm volatile("red.global.add.v4.f32 [%0], {%1,%2,%3,%4};"
                 :: "l"(ap), "f"(v.x), "f"(v.y), "f"(v.z), "f"(v.w) : "memory");
}

// ---------------- output head ----------------
__global__ void out_kernel(
    const float* __restrict__ pooled,
    const float* __restrict__ Wout,
    const float* __restrict__ bout,
    float*       __restrict__ out)
{
    int idx = blockIdx.x * blockDim.x + threadIdx.x;
    if (idx >= NUM_GRAPHS * N_CLASSES) return;
    int g = idx / N_CLASSES;
    int c = idx % N_CLASSES;
    float s = __ldg(bout + c);
    const float* p = pooled + (size_t)g * HIDDEN;
    const float* w = Wout + (size_t)c * HIDDEN;
#pragma unroll 8
    for (int k = 0; k < HIDDEN; ++k) s = fmaf(p[k], w[k], s);
    out[idx] = s;
}

// ---------------- launch ----------------
extern "C" void kernel_launch(void* const* d_in, const int* in_sizes, int n_in,
                              void* d_out, int out_size)
{
    const float* x     = (const float*)d_in[0];
    const int*   ei    = (const int*)  d_in[1];
    const int*   batch = (const int*)  d_in[2];
    const float* W1l = (const float*)d_in[3];
    const float* b1  = (const float*)d_in[4];
    const float* W1r = (const float*)d_in[5];
    const float* W2l = (const float*)d_in[6];
    const float* b2  = (const float*)d_in[7];
    const float* W2r = (const float*)d_in[8];
    const float* W3l = (const float*)d_in[9];
    const float* b3  = (const float*)d_in[10];
    const float* W3r = (const float*)d_in[11];
    const float* Wout = (const float*)d_in[12];
    const float* bout = (const float*)d_in[13];
    float* out = (float*)d_out;

    float *agg, *h1, *h2, *pooled;
    int *deg, *off, *cur, *srcs;
    cudaGetSymbolAddress((void**)&agg,    g_agg);
    cudaGetSymbolAddress((void**)&h1,     g_h1);
    cudaGetSymbolAddress((void**)&h2,     g_h2);
    cudaGetSymbolAddress((void**)&pooled, g_pooled);
    cudaGetSymbolAddress((void**)&deg,    g_deg);
    cudaGetSymbolAddress((void**)&off,    g_off);
    cudaGetSymbolAddress((void**)&cur,    g_cur);
    cudaGetSymbolAddress((void**)&srcs,   g_srcs);

    const int edge_blocks = (N_EDGES + 255) / 256;
    const int node_blocks = (N_NODES + 255) / 256;
    const int gemm_blocks = (N_NODES + BM - 1) / BM;
    const int warp_blocks = (N_NODES * 32 + 255) / 256;

    // CSR build (once, reused for all 3 layers)
    zero_deg_kernel<<<node_blocks, 256>>>(deg);
    hist_kernel<<<edge_blocks, 256>>>(ei, deg);
    scan_kernel<<<1, 1024>>>(deg, off, cur);
    fill_kernel<<<edge_blocks, 256>>>(ei, cur, srcs);

    // layer 1: x -> h1
    aggregate_kernel<<<warp_blocks, 256>>>(x, off, srcs, agg);
    sage_gemm_kernel<<<gemm_blocks, 256>>>(agg, x, W1l, W1r, b1, h1, 1);

    // layer 2: h1 -> h2
    aggregate_kernel<<<warp_blocks, 256>>>(h1, off, srcs, agg);
    sage_gemm_kernel<<<gemm_blocks, 256>>>(agg, h1, W2l, W2r, b2, h2, 1);

    // layer 3: h2 -> h1 (no relu)
    aggregate_kernel<<<warp_blocks, 256>>>(h2, off, srcs, agg);
    sage_gemm_kernel<<<gemm_blocks, 256>>>(agg, h2, W3l, W3r, b3, h1, 0);

    // pool + head
    cudaMemsetAsync(pooled, 0, NUM_GRAPHS * HIDDEN * sizeof(float));
    pool_kernel<<<warp_blocks, 256>>>(h1, batch, pooled);
    out_kernel<<<(NUM_GRAPHS * N_CLASSES + 127) / 128, 128>>>(pooled, Wout, bout, out);
}

// round 7
// speedup vs baseline: 1.4494x; 1.1529x over previous
#include <cuda_runtime.h>
#include <cuda_bf16.h>
#include <mma.h>
#include <cstdint>

using namespace nvcuda;

#define N_NODES   100000
#define N_EDGES   1600000
#define D_FEAT    128
#define HIDDEN    128
#define N_CLASSES 10
#define NUM_GRAPHS 64
#define N_PAD     100096   // 782 * 128, full-tile padding for direct wmma stores

// ---------------- scratch (no allocs allowed) ----------------
__device__ float g_agg[(size_t)N_PAD * HIDDEN];
__device__ float g_h1 [(size_t)N_PAD * HIDDEN];
__device__ float g_h2 [(size_t)N_PAD * HIDDEN];
__device__ float g_pooled[NUM_GRAPHS * HIDDEN];
__device__ int   g_deg [N_NODES];
__device__ int   g_off [N_NODES + 1];
__device__ int   g_cur [N_NODES];
__device__ int   g_srcs[N_EDGES];

// ---------------- CSR build ----------------
__global__ void __launch_bounds__(256) zero_deg_kernel(int* __restrict__ deg)
{
    int i = blockIdx.x * blockDim.x + threadIdx.x;
    if (i < N_NODES) deg[i] = 0;
}

__global__ void __launch_bounds__(256) hist_kernel(
    const int* __restrict__ ei, int* __restrict__ deg)
{
    int e = blockIdx.x * blockDim.x + threadIdx.x;
    if (e >= N_EDGES) return;
    atomicAdd(deg + __ldg(ei + N_EDGES + e), 1);
}

__global__ void __launch_bounds__(1024) scan_kernel(
    const int* __restrict__ deg, int* __restrict__ off, int* __restrict__ cur)
{
    __shared__ int part[1024];
    const int tid = threadIdx.x;
    const int CH = (N_NODES + 1023) / 1024;
    const int start = tid * CH;
    int sum = 0;
    for (int i = 0; i < CH; ++i) {
        int idx = start + i;
        if (idx < N_NODES) sum += deg[idx];
    }
    part[tid] = sum;
    __syncthreads();
    for (int d = 1; d < 1024; d <<= 1) {
        int v = (tid >= d) ? part[tid - d] : 0;
        __syncthreads();
        part[tid] += v;
        __syncthreads();
    }
    int run = tid ? part[tid - 1] : 0;
    for (int i = 0; i < CH; ++i) {
        int idx = start + i;
        if (idx <= N_NODES) {
            off[idx] = run;
            if (idx < N_NODES) cur[idx] = run;
        }
        if (idx < N_NODES) run += deg[idx];
    }
}

__global__ void __launch_bounds__(256) fill_kernel(
    const int* __restrict__ ei, int* __restrict__ cur, int* __restrict__ srcs)
{
    int e = blockIdx.x * blockDim.x + threadIdx.x;
    if (e >= N_EDGES) return;
    int src = __ldg(ei + e);
    int dst = __ldg(ei + N_EDGES + e);
    int pos = atomicAdd(cur + dst, 1);
    srcs[pos] = src;
}

// ---------------- gather aggregation ----------------
__global__ void __launch_bounds__(256) aggregate_kernel(
    const float* __restrict__ h,
    const int*   __restrict__ off,
    const int*   __restrict__ srcs,
    float*       __restrict__ agg)
{
    int node = (blockIdx.x * blockDim.x + threadIdx.x) >> 5;
    int lane = threadIdx.x & 31;
    if (node >= N_NODES) return;
    int b = __ldg(off + node);
    int e = __ldg(off + node + 1);
    float4 acc = make_float4(0.f, 0.f, 0.f, 0.f);
    int i = b;
    for (; i + 3 < e; i += 4) {
        int s0 = __ldg(srcs + i + 0);
        int s1 = __ldg(srcs + i + 1);
        int s2 = __ldg(srcs + i + 2);
        int s3 = __ldg(srcs + i + 3);
        float4 v0 = __ldg(reinterpret_cast<const float4*>(h + (size_t)s0 * 128) + lane);
        float4 v1 = __ldg(reinterpret_cast<const float4*>(h + (size_t)s1 * 128) + lane);
        float4 v2 = __ldg(reinterpret_cast<const float4*>(h + (size_t)s2 * 128) + lane);
        float4 v3 = __ldg(reinterpret_cast<const float4*>(h + (size_t)s3 * 128) + lane);
        acc.x += (v0.x + v1.x) + (v2.x + v3.x);
        acc.y += (v0.y + v1.y) + (v2.y + v3.y);
        acc.z += (v0.z + v1.z) + (v2.z + v3.z);
        acc.w += (v0.w + v1.w) + (v2.w + v3.w);
    }
    for (; i < e; ++i) {
        int s = __ldg(srcs + i);
        float4 v = __ldg(reinterpret_cast<const float4*>(h + (size_t)s * 128) + lane);
        acc.x += v.x; acc.y += v.y; acc.z += v.z; acc.w += v.w;
    }
    *(reinterpret_cast<float4*>(agg + (size_t)node * 128) + lane) = acc;
}

// ================ WMMA bf16x2 SAGE GEMM ================
// out[m,n] = act( sum_k agg[m,k] Wl[n,k] + h[m,k] Wr[n,k] + b[n] )
// bf16 split: a = a_hi + a_lo;  D += Ah*Bh + Ah*Bl + Al*Bh  (fp32 accum)
// CTA: 128x128 tile, 8 warps in 2(m) x 4(n), warp tile 64x32.
// K processed in 4 chunks of 64: [agg k0-63][agg k64-127][h k0-63][h k64-127]

#define LDA 72                       // padded bf16 row length (64 + 8)
#define TILE_B  (128 * LDA * 2)      // 18432 bytes per bf16 tile
#define OFF_AHI 0
#define OFF_ALO (OFF_AHI + TILE_B)
#define OFF_BHI (OFF_ALO + TILE_B)
#define OFF_BLO (OFF_BHI + TILE_B)
#define OFF_BIAS (OFF_BLO + TILE_B)          // 16x128 f32 replicated bias
#define SM_TOTAL (OFF_BIAS + 16 * 128 * 4)   // 81920 bytes

__global__ void __launch_bounds__(256)
sage_wmma_kernel(
    const float* __restrict__ agg,
    const float* __restrict__ h,
    const float* __restrict__ Wl,
    const float* __restrict__ Wr,
    const float* __restrict__ bias,
    float*       __restrict__ out,   // padded to N_PAD rows
    int do_relu)
{
    extern __shared__ char smem[];
    __nv_bfloat16* sAhi = reinterpret_cast<__nv_bfloat16*>(smem + OFF_AHI);
    __nv_bfloat16* sAlo = reinterpret_cast<__nv_bfloat16*>(smem + OFF_ALO);
    __nv_bfloat16* sBhi = reinterpret_cast<__nv_bfloat16*>(smem + OFF_BHI);
    __nv_bfloat16* sBlo = reinterpret_cast<__nv_bfloat16*>(smem + OFF_BLO);
    float*         sBias = reinterpret_cast<float*>(smem + OFF_BIAS);

    const int tid = threadIdx.x;
    const int wid = tid >> 5;
    const int block_row = blockIdx.x * 128;

    // replicated bias (16 rows x 128 cols) for accumulator-fragment load
    for (int idx = tid; idx < 16 * 128; idx += 256)
        sBias[idx] = __ldg(bias + (idx & 127));

    // tile-load mapping: thread owns 32 contiguous cols of one row
    const int row  = tid >> 1;
    const int c0   = (tid & 1) * 32;
    const bool aok = (block_row + row) < N_NODES;

    // warp tile coordinates
    const int wm = (wid & 1) * 64;
    const int wn = (wid >> 1) * 32;

    wmma::fragment<wmma::accumulator, 16, 16, 16, float> acc[4][2];
#pragma unroll
    for (int i = 0; i < 4; ++i)
#pragma unroll
        for (int j = 0; j < 2; ++j) wmma::fill_fragment(acc[i][j], 0.f);

    // prefetch chunk 0
    float4 av[8], wv[8];
    {
        const float* ap = agg + (size_t)(block_row + row) * 128 + c0;
        const float* wp = Wl + (size_t)row * 128 + c0;
#pragma unroll
        for (int j = 0; j < 8; ++j) {
            av[j] = aok ? __ldg(reinterpret_cast<const float4*>(ap) + j)
                        : make_float4(0.f, 0.f, 0.f, 0.f);
            wv[j] = __ldg(reinterpret_cast<const float4*>(wp) + j);
        }
    }

#pragma unroll 1
    for (int c = 0; c < 4; ++c) {
        // convert prefetched fp32 -> bf16 hi/lo, store to SMEM
#pragma unroll
        for (int j = 0; j < 8; ++j) {
            int eoff = row * LDA + c0 + j * 4;
            __nv_bfloat162 h01, h23, l01, l23;
            h01.x = __float2bfloat16(av[j].x);
            h01.y = __float2bfloat16(av[j].y);
            h23.x = __float2bfloat16(av[j].z);
            h23.y = __float2bfloat16(av[j].w);
            l01.x = __float2bfloat16(av[j].x - __bfloat162float(h01.x));
            l01.y = __float2bfloat16(av[j].y - __bfloat162float(h01.y));
            l23.x = __float2bfloat16(av[j].z - __bfloat162float(h23.x));
            l23.y = __float2bfloat16(av[j].w - __bfloat162float(h23.y));
            *reinterpret_cast<__nv_bfloat162*>(sAhi + eoff)     = h01;
            *reinterpret_cast<__nv_bfloat162*>(sAhi + eoff + 2) = h23;
            *reinterpret_cast<__nv_bfloat162*>(sAlo + eoff)     = l01;
            *reinterpret_cast<__nv_bfloat162*>(sAlo + eoff + 2) = l23;
            h01.x = __float2bfloat16(wv[j].x);
            h01.y = __float2bfloat16(wv[j].y);
            h23.x = __float2bfloat16(wv[j].z);
            h23.y = __float2bfloat16(wv[j].w);
            l01.x = __float2bfloat16(wv[j].x - __bfloat162float(h01.x));
            l01.y = __float2bfloat16(wv[j].y - __bfloat162float(h01.y));
            l23.x = __float2bfloat16(wv[j].z - __bfloat162float(h23.x));
            l23.y = __float2bfloat16(wv[j].w - __bfloat162float(h23.y));
            *reinterpret_cast<__nv_bfloat162*>(sBhi + eoff)     = h01;
            *reinterpret_cast<__nv_bfloat162*>(sBhi + eoff + 2) = h23;
            *reinterpret_cast<__nv_bfloat162*>(sBlo + eoff)     = l01;
            *reinterpret_cast<__nv_bfloat162*>(sBlo + eoff + 2) = l23;
        }
        __syncthreads();

        // prefetch next chunk (overlaps with MMA below)
        if (c < 3) {
            const int nc = c + 1;
            const float* Asrc = (nc < 2) ? agg : h;
            const float* Wsrc = (nc < 2) ? Wl  : Wr;
            const int k0 = (nc & 1) * 64;
            const float* ap = Asrc + (size_t)(block_row + row) * 128 + k0 + c0;
            const float* wp = Wsrc + (size_t)row * 128 + k0 + c0;
#pragma unroll
            for (int j = 0; j < 8; ++j) {
                av[j] = aok ? __ldg(reinterpret_cast<const float4*>(ap) + j)
                            : make_float4(0.f, 0.f, 0.f, 0.f);
                wv[j] = __ldg(reinterpret_cast<const float4*>(wp) + j);
            }
        }

        // MMA over this chunk: 4 k-steps of 16
#pragma unroll
        for (int ks = 0; ks < 4; ++ks) {
            wmma::fragment<wmma::matrix_a, 16, 16, 16, __nv_bfloat16, wmma::row_major> fah[4], fal[4];
            wmma::fragment<wmma::matrix_b, 16, 16, 16, __nv_bfloat16, wmma::col_major> fbh[2], fbl[2];
#pragma unroll
            for (int i = 0; i < 4; ++i) {
                wmma::load_matrix_sync(fah[i], sAhi + (wm + i * 16) * LDA + ks * 16, LDA);
                wmma::load_matrix_sync(fal[i], sAlo + (wm + i * 16) * LDA + ks * 16, LDA);
            }
#pragma unroll
            for (int j = 0; j < 2; ++j) {
                wmma::load_matrix_sync(fbh[j], sBhi + (wn + j * 16) * LDA + ks * 16, LDA);
                wmma::load_matrix_sync(fbl[j], sBlo + (wn + j * 16) * LDA + ks * 16, LDA);
            }
#pragma unroll
            for (int i = 0; i < 4; ++i)
#pragma unroll
                for (int j = 0; j < 2; ++j) {
                    wmma::mma_sync(acc[i][j], fah[i], fbh[j], acc[i][j]);
                    wmma::mma_sync(acc[i][j], fah[i], fbl[j], acc[i][j]);
                    wmma::mma_sync(acc[i][j], fal[i], fbh[j], acc[i][j]);
                }
        }
        __syncthreads();
    }

    // epilogue: bias (+relu) in-fragment, store directly to padded GMEM
#pragma unroll
    for (int j = 0; j < 2; ++j) {
        wmma::fragment<wmma::accumulator, 16, 16, 16, float> bf;
        wmma::load_matrix_sync(bf, sBias + wn + j * 16, 128, wmma::mem_row_major);
#pragma unroll
        for (int i = 0; i < 4; ++i) {
#pragma unroll
            for (int e = 0; e < acc[i][j].num_elements; ++e) {
                float v = acc[i][j].x[e] + bf.x[e];
                acc[i][j].x[e] = do_relu ? fmaxf(v, 0.f) : v;
            }
            float* op = out + (size_t)(block_row + wm + i * 16) * 128 + wn + j * 16;
            wmma::store_matrix_sync(op, acc[i][j], 128, wmma::mem_row_major);
        }
    }
}

// ---------------- pooling ----------------
__global__ void __launch_bounds__(256) pool_kernel(
    const float* __restrict__ h,
    const int*   __restrict__ batch,
    float*       __restrict__ pooled)
{
    int node = (blockIdx.x * blockDim.x + threadIdx.x) >> 5;
    int lane = threadIdx.x & 31;
    if (node >= N_NODES) return;
    int g = __ldg(batch + node);
    float4 v = __ldg(reinterpret_cast<const float4*>(h + (size_t)node * HIDDEN) + lane);
    float* ap = pooled + (size_t)g * HIDDEN + lane * 4;
    asm volatile("red.global.add.v4.f32 [%0], {%1,%2,%3,%4};"
                 :: "l"(ap), "f"(v.x), "f"(v.y), "f"(v.z), "f"(v.w) : "memory");
}

// ---------------- output head ----------------
__global__ void out_kernel(
    const float* __restrict__ pooled,
    const float* __restrict__ Wout,
    const float* __restrict__ bout,
    float*       __restrict__ out)
{
    int idx = blockIdx.x * blockDim.x + threadIdx.x;
    if (idx >= NUM_GRAPHS * N_CLASSES) return;
    int g = idx / N_CLASSES;
    int c = idx % N_CLASSES;
    float s = __ldg(bout + c);
    const float* p = pooled + (size_t)g * HIDDEN;
    const float* w = Wout + (size_t)c * HIDDEN;
#pragma unroll 8
    for (int k = 0; k < HIDDEN; ++k) s = fmaf(p[k], w[k], s);
    out[idx] = s;
}

// ---------------- launch ----------------
extern "C" void kernel_launch(void* const* d_in, const int* in_sizes, int n_in,
                              void* d_out, int out_size)
{
    const float* x     = (const float*)d_in[0];
    const int*   ei    = (const int*)  d_in[1];
    const int*   batch = (const int*)  d_in[2];
    const float* W1l = (const float*)d_in[3];
    const float* b1  = (const float*)d_in[4];
    const float* W1r = (const float*)d_in[5];
    const float* W2l = (const float*)d_in[6];
    const float* b2  = (const float*)d_in[7];
    const float* W2r = (const float*)d_in[8];
    const float* W3l = (const float*)d_in[9];
    const float* b3  = (const float*)d_in[10];
    const float* W3r = (const float*)d_in[11];
    const float* Wout = (const float*)d_in[12];
    const float* bout = (const float*)d_in[13];
    float* out = (float*)d_out;

    float *agg, *h1, *h2, *pooled;
    int *deg, *off, *cur, *srcs;
    cudaGetSymbolAddress((void**)&agg,    g_agg);
    cudaGetSymbolAddress((void**)&h1,     g_h1);
    cudaGetSymbolAddress((void**)&h2,     g_h2);
    cudaGetSymbolAddress((void**)&pooled, g_pooled);
    cudaGetSymbolAddress((void**)&deg,    g_deg);
    cudaGetSymbolAddress((void**)&off,    g_off);
    cudaGetSymbolAddress((void**)&cur,    g_cur);
    cudaGetSymbolAddress((void**)&srcs,   g_srcs);

    cudaFuncSetAttribute(sage_wmma_kernel,
                         cudaFuncAttributeMaxDynamicSharedMemorySize, SM_TOTAL);

    const int edge_blocks = (N_EDGES + 255) / 256;
    const int node_blocks = (N_NODES + 255) / 256;
    const int gemm_blocks = N_PAD / 128;   // 782
    const int warp_blocks = (N_NODES * 32 + 255) / 256;

    // CSR build (once, reused for all 3 layers)
    zero_deg_kernel<<<node_blocks, 256>>>(deg);
    hist_kernel<<<edge_blocks, 256>>>(ei, deg);
    scan_kernel<<<1, 1024>>>(deg, off, cur);
    fill_kernel<<<edge_blocks, 256>>>(ei, cur, srcs);

    // layer 1: x -> h1
    aggregate_kernel<<<warp_blocks, 256>>>(x, off, srcs, agg);
    sage_wmma_kernel<<<gemm_blocks, 256, SM_TOTAL>>>(agg, x, W1l, W1r, b1, h1, 1);

    // layer 2: h1 -> h2
    aggregate_kernel<<<warp_blocks, 256>>>(h1, off, srcs, agg);
    sage_wmma_kernel<<<gemm_blocks, 256, SM_TOTAL>>>(agg, h1, W2l, W2r, b2, h2, 1);

    // layer 3: h2 -> h1 (no relu)
    aggregate_kernel<<<warp_blocks, 256>>>(h2, off, srcs, agg);
    sage_wmma_kernel<<<gemm_blocks, 256, SM_TOTAL>>>(agg, h2, W3l, W3r, b3, h1, 0);

    // pool + head
    cudaMemsetAsync(pooled, 0, NUM_GRAPHS * HIDDEN * sizeof(float));
    pool_kernel<<<warp_blocks, 256>>>(h1, batch, pooled);
    out_kernel<<<(NUM_GRAPHS * N_CLASSES + 127) / 128, 128>>>(pooled, Wout, bout, out);
}